// round 11
// baseline (speedup 1.0000x reference)
#include <cuda_runtime.h>
#include <cuda_bf16.h>
#include <cstdint>

// ---------------------------------------------------------------------------
// RSSM observe scan, GB300 — round 11.
//   k_pre_inp     : fp32 (R3-proven).
//   k_pre_obs_mma : split-bf16 mma.sync GEMM (R10-proven, ~140us).
//   k_rssm v7     : 32 clusters x 4 CTAs x 640 thr; 16 rows/cluster; every
//                   matmul column-sharded 4 ways (per-CTA weight bytes/step
//                   0.71 -> 0.39 MB). dn + stat-partial exchanges via DSMEM,
//                   2 cluster barriers/step.
// ---------------------------------------------------------------------------

#define Bc 512
#define Tc 64
#define Ec 1024
#define Ac 32
#define Sc 30
#define Dc 200
#define Hc 200
#define SSc 230
#define OUTC 380

typedef unsigned long long ull;

__device__ float g_pre_inp[Tc * Bc * Hc];
__device__ float g_pre_obs[Tc * Bc * Hc];

// ---- packed f32x2 helpers -------------------------------------------------
__device__ __forceinline__ ull pk2(float a, float b) {
    ull r; asm("mov.b64 %0, {%1, %2};" : "=l"(r) : "f"(a), "f"(b)); return r;
}
__device__ __forceinline__ ull dup2(float a) {
    ull r; asm("mov.b64 %0, {%1, %1};" : "=l"(r) : "f"(a)); return r;
}
__device__ __forceinline__ float2 up2(ull v) {
    float x, y; asm("mov.b64 {%0, %1}, %2;" : "=f"(x), "=f"(y) : "l"(v));
    return make_float2(x, y);
}
__device__ __forceinline__ void fma2(ull& acc, ull a, ull b) {
    asm("fma.rn.f32x2 %0, %1, %2, %0;" : "+l"(acc) : "l"(a), "l"(b));
}

__device__ __forceinline__ float sigm(float x) { return 1.0f / (1.0f + __expf(-x)); }
__device__ __forceinline__ float eluf(float x) { return x > 0.0f ? x : (__expf(x) - 1.0f); }
__device__ __forceinline__ float softplusf(float x) {
    return x > 15.0f ? x : log1pf(__expf(x));
}

// ---- cluster / smem helpers -------------------------------------------------
__device__ __forceinline__ uint32_t smem_u32(const void* p) {
    uint32_t a;
    asm("{ .reg .u64 t; cvta.to.shared.u64 t, %1; cvt.u32.u64 %0, t; }"
        : "=r"(a) : "l"(p));
    return a;
}
__device__ __forceinline__ void st_peer_u64(uint32_t laddr, uint32_t rank, ull v) {
    uint32_t ra;
    asm volatile("mapa.shared::cluster.u32 %0, %1, %2;" : "=r"(ra)
                 : "r"(laddr), "r"(rank));
    asm volatile("st.shared::cluster.u64 [%0], %1;" :: "r"(ra), "l"(v) : "memory");
}
__device__ __forceinline__ uint32_t ctarank() {
    uint32_t r; asm("mov.u32 %0, %%cluster_ctarank;" : "=r"(r)); return r;
}
#define CB() do { asm volatile("barrier.cluster.arrive.aligned;" ::: "memory"); \
                  asm volatile("barrier.cluster.wait.aligned;" ::: "memory"); } while (0)

// ---- mma.sync helpers (compute_103-legal) -----------------------------------
__device__ __forceinline__ void ldmx4(uint32_t* a, uint32_t addr) {
    asm volatile("ldmatrix.sync.aligned.m8n8.x4.shared.b16 {%0,%1,%2,%3}, [%4];"
                 : "=r"(a[0]), "=r"(a[1]), "=r"(a[2]), "=r"(a[3]) : "r"(addr));
}
__device__ __forceinline__ void ldmx2(uint32_t* a, uint32_t addr) {
    asm volatile("ldmatrix.sync.aligned.m8n8.x2.shared.b16 {%0,%1}, [%2];"
                 : "=r"(a[0]), "=r"(a[1]) : "r"(addr));
}
__device__ __forceinline__ void mma16816(float* c, const uint32_t* a,
                                         const uint32_t* b) {
    asm volatile(
        "mma.sync.aligned.m16n8k16.row.col.f32.bf16.bf16.f32 "
        "{%0,%1,%2,%3},{%4,%5,%6,%7},{%8,%9},{%0,%1,%2,%3};"
        : "+f"(c[0]), "+f"(c[1]), "+f"(c[2]), "+f"(c[3])
        : "r"(a[0]), "r"(a[1]), "r"(a[2]), "r"(a[3]), "r"(b[0]), "r"(b[1]));
}

// ===========================================================================
// k_pre_obs_mma (unchanged from R10)
// ===========================================================================
__global__ void __launch_bounds__(512, 1)
k_pre_obs_mma(const float* __restrict__ embed,
              const float* __restrict__ w_obs,
              const float* __restrict__ b_obs) {
    __shared__ __align__(16) __nv_bfloat16 sAhi[128 * 24];
    __shared__ __align__(16) __nv_bfloat16 sAlo[128 * 24];
    __shared__ __align__(16) __nv_bfloat16 sBhi[200 * 24];
    __shared__ __align__(16) __nv_bfloat16 sBlo[200 * 24];
    __shared__ float sbias[200];

    const int tid = threadIdx.x;
    const int wid = tid >> 5, lane = tid & 31;
    const int row0 = blockIdx.x * 128;

    const int ar = tid >> 2;
    const int akq = (tid & 3) * 4;
    const int arg = row0 + ar;
    const float* aSrc =
        embed + ((size_t)((arg & 511) * Tc + (arg >> 9))) * Ec + akq;
    int bk[7], bn[7];
#pragma unroll
    for (int j = 0; j < 7; j++) {
        int idx = tid + j * 512;
        bk[j] = idx / 200; bn[j] = idx - bk[j] * 200;
    }

    for (int i = tid; i < Hc; i += 512) sbias[i] = b_obs[i];

    const int mtile = wid >> 1;
    const int ntb = (wid & 1) * 13;
    const int ncnt = (wid & 1) ? 12 : 13;
    const uint32_t aoff =
        (uint32_t)(((mtile * 16 + (lane & 15)) * 24 + (lane >> 4) * 8) * 2);
    const uint32_t aHiAddr = smem_u32(sAhi) + aoff;
    const uint32_t aLoAddr = smem_u32(sAlo) + aoff;
    const uint32_t boff =
        (uint32_t)((((lane & 7)) * 24 + ((lane >> 3) & 1) * 8) * 2);
    const uint32_t bHiBase = smem_u32(sBhi) + boff + (uint32_t)(ntb * 8 * 48);
    const uint32_t bLoBase = smem_u32(sBlo) + boff + (uint32_t)(ntb * 8 * 48);

    float acc[13][4];
#pragma unroll
    for (int q = 0; q < 13; q++)
#pragma unroll
        for (int i = 0; i < 4; i++) acc[q][i] = 0.0f;

    float araw[4], braw[7];
    {
        float4 v = *reinterpret_cast<const float4*>(aSrc);
        araw[0] = v.x; araw[1] = v.y; araw[2] = v.z; araw[3] = v.w;
#pragma unroll
        for (int j = 0; j < 7; j++)
            if (tid + j * 512 < 3200)
                braw[j] = w_obs[(size_t)(Dc + bk[j]) * Hc + bn[j]];
    }

    for (int ck = 0; ck < 64; ck++) {
        {
            __nv_bfloat16* ah = sAhi + ar * 24 + akq;
            __nv_bfloat16* al = sAlo + ar * 24 + akq;
#pragma unroll
            for (int i = 0; i < 4; i++) {
                __nv_bfloat16 h = __float2bfloat16(araw[i]);
                ah[i] = h;
                al[i] = __float2bfloat16(araw[i] - __bfloat162float(h));
            }
#pragma unroll
            for (int j = 0; j < 7; j++) {
                if (tid + j * 512 < 3200) {
                    __nv_bfloat16 h = __float2bfloat16(braw[j]);
                    sBhi[bn[j] * 24 + bk[j]] = h;
                    sBlo[bn[j] * 24 + bk[j]] =
                        __float2bfloat16(braw[j] - __bfloat162float(h));
                }
            }
        }
        __syncthreads();

        if (ck < 63) {
            const int k0n = (ck + 1) * 16;
            float4 v = *reinterpret_cast<const float4*>(aSrc + k0n);
            araw[0] = v.x; araw[1] = v.y; araw[2] = v.z; araw[3] = v.w;
#pragma unroll
            for (int j = 0; j < 7; j++)
                if (tid + j * 512 < 3200)
                    braw[j] = w_obs[(size_t)(Dc + k0n + bk[j]) * Hc + bn[j]];
        }

        {
            uint32_t ah[4], al[4];
            ldmx4(ah, aHiAddr);
            ldmx4(al, aLoAddr);
#pragma unroll
            for (int q = 0; q < 13; q++) {
                if (q < ncnt) {
                    uint32_t bh[2], bl[2];
                    ldmx2(bh, bHiBase + (uint32_t)q * 384);
                    ldmx2(bl, bLoBase + (uint32_t)q * 384);
                    mma16816(acc[q], ah, bh);
                    mma16816(acc[q], al, bh);
                    mma16816(acc[q], ah, bl);
                }
            }
        }
        __syncthreads();
    }

    {
        const int gq = lane >> 2, t4 = lane & 3;
        const int m0 = row0 + mtile * 16 + gq;
#pragma unroll
        for (int q = 0; q < 13; q++) {
            if (q < ncnt) {
                const int n = (ntb + q) * 8 + 2 * t4;
                const float b0 = sbias[n], b1 = sbias[n + 1];
                *reinterpret_cast<float2*>(g_pre_obs + (size_t)m0 * Hc + n) =
                    make_float2(acc[q][0] + b0, acc[q][1] + b1);
                *reinterpret_cast<float2*>(g_pre_obs + (size_t)(m0 + 8) * Hc + n) =
                    make_float2(acc[q][2] + b0, acc[q][3] + b1);
            }
        }
    }
}

// ===========================================================================
// k_pre_inp: fp32, R3-proven variant
// ===========================================================================
__global__ void __launch_bounds__(128) k_pre_inp(const float* __restrict__ ctx,
                                                 const float* __restrict__ actn,
                                                 const float* __restrict__ w_inp,
                                                 const float* __restrict__ b_inp) {
    __shared__ __align__(8) float As[16][66];
    const int tid = threadIdx.x;
    const int jp = tid & 31, rg = tid >> 5;
    const int row0 = blockIdx.x * 64;
    const int j0 = blockIdx.y * 64 + jp * 2;
    const bool act = (j0 < Hc);
    const int rbase = rg * 16;

    ull acc[16];
#pragma unroll
    for (int i = 0; i < 16; i++) acc[i] = 0ull;

    for (int k0 = 0; k0 < 272; k0 += 16) {
#pragma unroll
        for (int i = 0; i < 8; i++) {
            int lin = tid + i * 128;
            int kk = lin & 15, r = lin >> 4;
            int rowg = row0 + r;
            int tt = rowg >> 9, bb = rowg & 511;
            int k = k0 + kk;
            float v = 0.0f;
            if (k < SSc)            v = ctx[(size_t)(bb * Tc + tt) * SSc + k];
            else if (k < SSc + Ac)  v = actn[(size_t)(bb * Tc + tt) * Ac + (k - SSc)];
            As[kk][r] = v;
        }
        __syncthreads();
        if (act) {
#pragma unroll
            for (int kk = 0; kk < 16; kk++) {
                int kw = (k0 + kk < SSc + Ac) ? (k0 + kk) : (SSc + Ac - 1);
                float2 w = *reinterpret_cast<const float2*>(
                    w_inp + (size_t)(Sc + kw) * Hc + j0);
                ull wx = dup2(w.x), wy = dup2(w.y);
                const ull* ap = reinterpret_cast<const ull*>(&As[kk][rbase]);
#pragma unroll
                for (int pq = 0; pq < 8; pq++) {
                    ull a = ap[pq];
                    fma2(acc[2 * pq], a, wx);
                    fma2(acc[2 * pq + 1], a, wy);
                }
            }
        }
        __syncthreads();
    }
    if (act) {
        float bx = b_inp[j0], by = b_inp[j0 + 1];
#pragma unroll
        for (int pq = 0; pq < 8; pq++) {
            float2 va = up2(acc[2 * pq]), vb = up2(acc[2 * pq + 1]);
            int r = row0 + rbase + 2 * pq;
            *reinterpret_cast<float2*>(g_pre_inp + (size_t)r * Hc + j0) =
                make_float2(va.x + bx, vb.x + by);
            *reinterpret_cast<float2*>(g_pre_inp + (size_t)(r + 1) * Hc + j0) =
                make_float2(va.y + bx, vb.y + by);
        }
    }
}

// ===========================================================================
// k_rssm v7 — 4-CTA clusters, 16 rows/cluster, columns sharded /4.
// smem (bytes):
//  XD   ull[400][16] @      0 (51200)  x||d dup
//  DN   ull[200][16] @  51200 (25600)  deter_new dup (full via exchange)
//  HHO  ull[100][16] @  76800 (12800)  local h(50)||ho(50) dup
//  PART 5100 ull     @  89600 (40800)  k-split partials, 17-ull stride
//  STP  [4][120][16]f@ 130400 (30720)  stat partials by source CTA
//  STF  [32][16] f   @ 161120 ( 2048)  stoch carry
//  BGRU 600f @163168, BIMG 200f @165568, BIMS 64f @166368, BOBS 64f @166624
// ===========================================================================
#define XD_OFF   0
#define DN_OFF   51200
#define HHO_OFF  76800
#define PART_OFF 89600
#define STP_OFF  130400
#define STF_OFF  161120
#define BGRU_OFF 163168
#define BIMG_OFF 165568
#define BIMS_OFF 166368
#define BOBS_OFF 166624
#define SMEM_BYTES 166880

__global__ void __launch_bounds__(640, 1) __cluster_dims__(4, 1, 1) k_rssm(
    const float* __restrict__ noise_p, const float* __restrict__ noise_o,
    const float* __restrict__ w_inp,  const float* __restrict__ w_gru,
    const float* __restrict__ b_gru_g,
    const float* __restrict__ w_img,  const float* __restrict__ b_img_g,
    const float* __restrict__ w_obsd,
    const float* __restrict__ w_ims,  const float* __restrict__ b_ims_g,
    const float* __restrict__ w_obst, const float* __restrict__ b_obst_g,
    float* __restrict__ out) {
    extern __shared__ __align__(16) char sm[];
    ull*   xd_u  = reinterpret_cast<ull*>(sm + XD_OFF);
    ull*   dn_u  = reinterpret_cast<ull*>(sm + DN_OFF);
    ull*   hho_u = reinterpret_cast<ull*>(sm + HHO_OFF);
    ull*   part_u = reinterpret_cast<ull*>(sm + PART_OFF);
    float* part_f = reinterpret_cast<float*>(sm + PART_OFF);
    float* stpf  = reinterpret_cast<float*>(sm + STP_OFF);
    float* st_f  = reinterpret_cast<float*>(sm + STF_OFF);
    float* bgru  = reinterpret_cast<float*>(sm + BGRU_OFF);
    float* bimg  = reinterpret_cast<float*>(sm + BIMG_OFF);
    float* bims  = reinterpret_cast<float*>(sm + BIMS_OFF);
    float* bobs  = reinterpret_cast<float*>(sm + BOBS_OFF);
    const ulonglong2* xd_u2  = reinterpret_cast<const ulonglong2*>(xd_u);
    const ulonglong2* dn_u2  = reinterpret_cast<const ulonglong2*>(dn_u);
    const ulonglong2* hho_u2 = reinterpret_cast<const ulonglong2*>(hho_u);
    const float* dn_f = reinterpret_cast<const float*>(dn_u);
    const float* xd_f = reinterpret_cast<const float*>(xd_u);

    const int tid = threadIdx.x;
    const int p = (int)ctarank();            // 0..3
    const int rb = (blockIdx.x >> 2) * 16;   // 16 rows per cluster
    const uint32_t base32 = smem_u32(sm);

    for (int i = tid; i < 600; i += 640) bgru[i] = b_gru_g[i];
    for (int i = tid; i < Hc; i += 640) bimg[i] = b_img_g[i];
    if (tid < 60) { bims[tid] = b_ims_g[tid]; bobs[tid] = b_obst_g[tid]; }
    for (int i = tid; i < 3200; i += 640) xd_u[3200 + i] = 0ull;   // d = 0
    for (int i = tid; i < 512; i += 640) st_f[i] = 0.0f;           // stoch = 0
    __syncthreads();
    CB();

    for (int t = 0; t < Tc; t++) {
        // ---- P1: x = elu(stoch @ Wis + pre_inp[t]) — full, 16 rows ----
        if (tid < 400) {
            const int j = tid >> 1, rh = tid & 1;   // rows rh*8 .. rh*8+7
            const float* pi = g_pre_inp + ((size_t)t * Bc + rb) * Hc + j;
            float a[8];
#pragma unroll
            for (int i = 0; i < 8; i++) a[i] = pi[(rh * 8 + i) * Hc];
#pragma unroll
            for (int k = 0; k < Sc; k++) {
                float w = w_inp[k * Hc + j];
                float4 s0 = *reinterpret_cast<const float4*>(&st_f[k * 16 + rh * 8]);
                float4 s1 = *reinterpret_cast<const float4*>(&st_f[k * 16 + rh * 8 + 4]);
                a[0] = fmaf(w, s0.x, a[0]); a[1] = fmaf(w, s0.y, a[1]);
                a[2] = fmaf(w, s0.z, a[2]); a[3] = fmaf(w, s0.w, a[3]);
                a[4] = fmaf(w, s1.x, a[4]); a[5] = fmaf(w, s1.y, a[5]);
                a[6] = fmaf(w, s1.z, a[6]); a[7] = fmaf(w, s1.w, a[7]);
            }
            ull* xo = &xd_u[j * 16 + rh * 8];
#pragma unroll
            for (int i = 0; i < 8; i++) xo[i] = dup2(eluf(a[i]));
        }
        __syncthreads();

        // ---- P2: GRU partials, our 150 gate-cols (2-col pairs), k-split 4 ----
        if (tid < 600) {
            const int cp = tid % 75;
            const int z = tid / 75;
            const int rh = z & 1, seg = z >> 1;
            const int gate = cp / 25, cpg = cp - gate * 25;
            const int gcol = gate * 200 + p * 50 + cpg * 2;
            const float* W = w_gru + (size_t)(seg * 100) * 600 + gcol;
            const ulonglong2* Ap = xd_u2 + (seg * 100) * 8 + rh * 4;
            ull A0 = 0, A1 = 0, A2 = 0, A3 = 0, A4 = 0, A5 = 0, A6 = 0, A7 = 0;
#pragma unroll 4
            for (int kk = 0; kk < 100; kk++) {
                ull w = *reinterpret_cast<const ull*>(W + (size_t)kk * 600);
                ulonglong2 a0 = Ap[kk * 8], a1 = Ap[kk * 8 + 1];
                ulonglong2 a2 = Ap[kk * 8 + 2], a3 = Ap[kk * 8 + 3];
                fma2(A0, a0.x, w); fma2(A1, a0.y, w);
                fma2(A2, a1.x, w); fma2(A3, a1.y, w);
                fma2(A4, a2.x, w); fma2(A5, a2.y, w);
                fma2(A6, a3.x, w); fma2(A7, a3.y, w);
            }
            ull* P = part_u + (seg * 75 + cp) * 17 + rh * 8;
            P[0] = A0; P[1] = A1; P[2] = A2; P[3] = A3;
            P[4] = A4; P[5] = A5; P[6] = A6; P[7] = A7;
        }
        __syncthreads();

        // ---- C2: gates -> deter_new (our 50 cols), dup to all 4 CTAs ----
        if (tid < 400) {
            const int j = tid >> 3, q = tid & 7;   // rows 2q, 2q+1
            const int gd = p * 50 + j;
            const int jp2 = j >> 1, e = j & 1;
            const int cpR = jp2, cpC = 25 + jp2, cpU = 50 + jp2;
            const float bR = bgru[gd], bC = bgru[200 + gd], bU = bgru[400 + gd];
#pragma unroll
            for (int w2 = 0; w2 < 2; w2++) {
                const int r = 2 * q + w2;
                float R = bR, C = bC, U = bU - 1.0f;
#pragma unroll
                for (int seg = 0; seg < 4; seg++) {
                    R += part_f[(((seg * 75 + cpR) * 17 + r) << 1) + e];
                    C += part_f[(((seg * 75 + cpC) * 17 + r) << 1) + e];
                    U += part_f[(((seg * 75 + cpU) * 17 + r) << 1) + e];
                }
                float reset = sigm(R);
                float cand  = tanhf(reset * C);
                float upd   = sigm(U);
                float dprev = xd_f[((200 + gd) * 16 + r) * 2];
                float dnv = upd * cand + (1.0f - upd) * dprev;
                ull dv = dup2(dnv);
                dn_u[gd * 16 + r] = dv;
#pragma unroll
                for (int pr = 0; pr < 4; pr++)
                    if (pr != p)
                        st_peer_u64(base32 + DN_OFF + (uint32_t)(gd * 16 + r) * 8,
                                    (uint32_t)pr, dv);
            }
        }
        CB();   // dn full in all 4 CTAs

        // ---- P3: h/ho partials (our 50+50 cols, k-split 4) ∥ deter out+carry --
        if (tid < 400) {
            const int cp = tid % 50;
            const int z = tid / 50;
            const int rh = z & 1, seg = z >> 1;
            const bool ish = cp < 25;
            const int cpl = ish ? cp : cp - 25;
            const int gcol = p * 50 + cpl * 2;
            const float* W = (ish ? w_img : w_obsd) + (size_t)(seg * 50) * Hc + gcol;
            const ulonglong2* Ap = dn_u2 + (seg * 50) * 8 + rh * 4;
            ull A0 = 0, A1 = 0, A2 = 0, A3 = 0, A4 = 0, A5 = 0, A6 = 0, A7 = 0;
#pragma unroll 4
            for (int kk = 0; kk < 50; kk++) {
                ull w = *reinterpret_cast<const ull*>(W + (size_t)kk * Hc);
                ulonglong2 a0 = Ap[kk * 8], a1 = Ap[kk * 8 + 1];
                ulonglong2 a2 = Ap[kk * 8 + 2], a3 = Ap[kk * 8 + 3];
                fma2(A0, a0.x, w); fma2(A1, a0.y, w);
                fma2(A2, a1.x, w); fma2(A3, a1.y, w);
                fma2(A4, a2.x, w); fma2(A5, a2.y, w);
                fma2(A6, a3.x, w); fma2(A7, a3.y, w);
            }
            ull* P = part_u + (seg * 50 + cp) * 17 + rh * 8;
            P[0] = A0; P[1] = A1; P[2] = A2; P[3] = A3;
            P[4] = A4; P[5] = A5; P[6] = A6; P[7] = A7;
        } else {
            const int tt2 = tid - 400;   // 0..239
            // deter gmem: our 4 rows
            for (int i = tt2; i < 800; i += 240) {
                const int rl = i / 200, jj = i % 200;
                out[((size_t)(rb + p * 4 + rl) * Tc + t) * OUTC + 180 + jj] =
                    dn_f[(jj * 16 + p * 4 + rl) * 2];
            }
            // carry: xd d-part <- deter_new (full)
            for (int i = tt2; i < 3200; i += 240) xd_u[3200 + i] = dn_u[i];
        }
        __syncthreads();

        // ---- C3: reduce + bias/pre_obs + elu -> local hho dup ----
        if (tid < 400) {
            const int cl = tid >> 2, qq = tid & 3;   // rows 4qq..4qq+3
            const bool ish = cl < 50;
            const int jl = ish ? cl : cl - 50;
            const int gcol = p * 50 + jl;
            const int cp = (ish ? 0 : 25) + (jl >> 1);
            const int e = jl & 1;
            const float* po = g_pre_obs + ((size_t)t * Bc + rb) * Hc + gcol;
            const float bb = ish ? bimg[gcol] : 0.0f;
#pragma unroll
            for (int i = 0; i < 4; i++) {
                const int r = 4 * qq + i;
                float v = ish ? bb : po[r * Hc];
#pragma unroll
                for (int seg = 0; seg < 4; seg++)
                    v += part_f[(((seg * 50 + cp) * 17 + r) << 1) + e];
                hho_u[cl * 16 + r] = dup2(eluf(v));
            }
        }
        __syncthreads();

        // ---- P4: stat partials over local K-slices (2 segs of 25) ----
        if (tid < 240) {
            const int cp = tid % 60;
            const int z = tid / 60;                 // 0..3
            const int rh = z & 1, seg = z >> 1;     // seg 0..1
            const bool post = cp >= 30;
            const int cpl = post ? cp - 30 : cp;
            const int c2 = cpl * 2;
            const float* W = (post ? w_obst : w_ims) +
                             (size_t)(p * 50 + seg * 25) * 60 + c2;
            const ulonglong2* Ap = hho_u2 +
                                   ((post ? 50 : 0) + seg * 25) * 8 + rh * 4;
            ull A0 = 0, A1 = 0, A2 = 0, A3 = 0, A4 = 0, A5 = 0, A6 = 0, A7 = 0;
#pragma unroll 5
            for (int kk = 0; kk < 25; kk++) {
                ull w = *reinterpret_cast<const ull*>(W + (size_t)kk * 60);
                ulonglong2 a0 = Ap[kk * 8], a1 = Ap[kk * 8 + 1];
                ulonglong2 a2 = Ap[kk * 8 + 2], a3 = Ap[kk * 8 + 3];
                fma2(A0, a0.x, w); fma2(A1, a0.y, w);
                fma2(A2, a1.x, w); fma2(A3, a1.y, w);
                fma2(A4, a2.x, w); fma2(A5, a2.y, w);
                fma2(A6, a3.x, w); fma2(A7, a3.y, w);
            }
            ull* P = part_u + (seg * 60 + cp) * 17 + rh * 8;
            P[0] = A0; P[1] = A1; P[2] = A2; P[3] = A3;
            P[4] = A4; P[5] = A5; P[6] = A6; P[7] = A7;
        }
        __syncthreads();

        // ---- C4: reduce 2 segs -> stat partial slot p; send to 3 peers ----
        if (tid < 240) {
            const int c = tid >> 1, rh = tid & 1;    // rows rh*8..rh*8+7
            const bool post = c >= 60;
            const int cl = post ? c - 60 : c;
            const int cp = (post ? 30 : 0) + (cl >> 1);
            const int e = cl & 1;
            float v[8];
#pragma unroll
            for (int i = 0; i < 8; i++) {
                const int r = rh * 8 + i;
                v[i] = part_f[((cp * 17 + r) << 1) + e] +
                       part_f[(((60 + cp) * 17 + r) << 1) + e];
            }
#pragma unroll
            for (int w2 = 0; w2 < 4; w2++) {
                ull u = pk2(v[2 * w2], v[2 * w2 + 1]);
                const uint32_t idx =
                    (uint32_t)(p * 1920 + c * 16 + rh * 8 + 2 * w2);
                *reinterpret_cast<ull*>(stpf + idx) = u;
#pragma unroll
                for (int pr = 0; pr < 4; pr++)
                    if (pr != p)
                        st_peer_u64(base32 + STP_OFF + idx * 4, (uint32_t)pr, u);
            }
        }
        CB();   // stat partials full everywhere

        // ---- P5: sample + outputs + carry ----
        if (tid < 480) {
            const int r = tid / 30, k = tid - r * 30;
            const int b = rb + r;
            float pm = bims[k], psv = bims[30 + k];
            float om = bobs[k], osv = bobs[30 + k];
#pragma unroll
            for (int slot = 0; slot < 4; slot++) {
                const float* sp = stpf + slot * 1920;
                pm  += sp[k * 16 + r];
                psv += sp[(30 + k) * 16 + r];
                om  += sp[(60 + k) * 16 + r];
                osv += sp[(90 + k) * 16 + r];
            }
            psv = softplusf(psv) + 0.1f;
            osv = softplusf(osv) + 0.1f;
            float ost = fmaf(osv, noise_o[((size_t)t * Bc + b) * Sc + k], om);
            float pst = fmaf(psv, noise_p[((size_t)t * Bc + b) * Sc + k], pm);
            st_f[k * 16 + r] = ost;
            if ((r >> 2) == p) {
                size_t basep = ((size_t)b * Tc + t) * OUTC;
                out[basep + k]       = om;
                out[basep + 30 + k]  = osv;
                out[basep + 60 + k]  = ost;
                out[basep + 90 + k]  = pm;
                out[basep + 120 + k] = psv;
                out[basep + 150 + k] = pst;
            }
        }
        __syncthreads();
    }
}

// ===========================================================================
extern "C" void kernel_launch(void* const* d_in, const int* in_sizes, int n_in,
                              void* d_out, int out_size) {
    const float* embed       = (const float*)d_in[0];
    const float* action      = (const float*)d_in[1];
    const float* context     = (const float*)d_in[2];
    const float* noise_prior = (const float*)d_in[3];
    const float* noise_post  = (const float*)d_in[4];
    const float* w_inp       = (const float*)d_in[5];
    const float* b_inp       = (const float*)d_in[6];
    const float* w_gru       = (const float*)d_in[7];
    const float* b_gru       = (const float*)d_in[8];
    const float* w_img_out   = (const float*)d_in[9];
    const float* b_img_out   = (const float*)d_in[10];
    const float* w_obs_out   = (const float*)d_in[11];
    const float* b_obs_out   = (const float*)d_in[12];
    const float* w_ims_stat  = (const float*)d_in[13];
    const float* b_ims_stat  = (const float*)d_in[14];
    const float* w_obs_stat  = (const float*)d_in[15];
    const float* b_obs_stat  = (const float*)d_in[16];
    float* out = (float*)d_out;

    static int smem_set = 0;
    if (!smem_set) {
        cudaFuncSetAttribute(k_rssm, cudaFuncAttributeMaxDynamicSharedMemorySize,
                             SMEM_BYTES);
        smem_set = 1;
    }

    k_pre_inp<<<dim3(Bc * Tc / 64, 4), 128>>>(context, action, w_inp, b_inp);
    k_pre_obs_mma<<<Bc * Tc / 128, 512>>>(embed, w_obs_out, b_obs_out);
    k_rssm<<<128, 640, SMEM_BYTES>>>(noise_prior, noise_post, w_inp, w_gru,
                                     b_gru, w_img_out, b_img_out, w_obs_out,
                                     w_ims_stat, b_ims_stat, w_obs_stat,
                                     b_obs_stat, out);
}

// round 12
// speedup vs baseline: 1.2376x; 1.2376x over previous
#include <cuda_runtime.h>
#include <cuda_bf16.h>
#include <cstdint>

// ---------------------------------------------------------------------------
// RSSM observe scan, GB300 — round 12.
//   k_pre_inp_mma : split-bf16 mma.sync GEMM, K=262 (pad 272), NEW this round.
//   k_pre_obs_mma : split-bf16 mma.sync GEMM (R10-proven, ~140us). UNCHANGED.
//   k_rssm        : exact R6/R10 v4 scan (proven best, ~1.70ms). UNCHANGED.
// ---------------------------------------------------------------------------

#define Bc 512
#define Tc 64
#define Ec 1024
#define Ac 32
#define Sc 30
#define Dc 200
#define Hc 200
#define SSc 230
#define OUTC 380

typedef unsigned long long ull;

__device__ float g_pre_inp[Tc * Bc * Hc];
__device__ float g_pre_obs[Tc * Bc * Hc];

// ---- packed f32x2 helpers -------------------------------------------------
__device__ __forceinline__ ull pk2(float a, float b) {
    ull r; asm("mov.b64 %0, {%1, %2};" : "=l"(r) : "f"(a), "f"(b)); return r;
}
__device__ __forceinline__ ull dup2(float a) {
    ull r; asm("mov.b64 %0, {%1, %1};" : "=l"(r) : "f"(a)); return r;
}
__device__ __forceinline__ float2 up2(ull v) {
    float x, y; asm("mov.b64 {%0, %1}, %2;" : "=f"(x), "=f"(y) : "l"(v));
    return make_float2(x, y);
}
__device__ __forceinline__ void fma2(ull& acc, ull a, ull b) {
    asm("fma.rn.f32x2 %0, %1, %2, %0;" : "+l"(acc) : "l"(a), "l"(b));
}

__device__ __forceinline__ float sigm(float x) { return 1.0f / (1.0f + __expf(-x)); }
__device__ __forceinline__ float eluf(float x) { return x > 0.0f ? x : (__expf(x) - 1.0f); }
__device__ __forceinline__ float softplusf(float x) {
    return x > 15.0f ? x : log1pf(__expf(x));
}

// ---- cluster / smem helpers -------------------------------------------------
__device__ __forceinline__ uint32_t smem_u32(const void* p) {
    uint32_t a;
    asm("{ .reg .u64 t; cvta.to.shared.u64 t, %1; cvt.u32.u64 %0, t; }"
        : "=r"(a) : "l"(p));
    return a;
}
__device__ __forceinline__ void st_peer_u64(uint32_t laddr, uint32_t rank, ull v) {
    uint32_t ra;
    asm volatile("mapa.shared::cluster.u32 %0, %1, %2;" : "=r"(ra)
                 : "r"(laddr), "r"(rank));
    asm volatile("st.shared::cluster.u64 [%0], %1;" :: "r"(ra), "l"(v) : "memory");
}
__device__ __forceinline__ void st_peer_f32(uint32_t laddr, uint32_t rank, float v) {
    uint32_t ra;
    asm volatile("mapa.shared::cluster.u32 %0, %1, %2;" : "=r"(ra)
                 : "r"(laddr), "r"(rank));
    asm volatile("st.shared::cluster.f32 [%0], %1;" :: "r"(ra), "f"(v) : "memory");
}
__device__ __forceinline__ uint32_t ctarank() {
    uint32_t r; asm("mov.u32 %0, %%cluster_ctarank;" : "=r"(r)); return r;
}
#define CB() do { asm volatile("barrier.cluster.arrive.aligned;" ::: "memory"); \
                  asm volatile("barrier.cluster.wait.aligned;" ::: "memory"); } while (0)

// ---- mma.sync helpers (compute_103-legal) -----------------------------------
__device__ __forceinline__ void ldmx4(uint32_t* a, uint32_t addr) {
    asm volatile("ldmatrix.sync.aligned.m8n8.x4.shared.b16 {%0,%1,%2,%3}, [%4];"
                 : "=r"(a[0]), "=r"(a[1]), "=r"(a[2]), "=r"(a[3]) : "r"(addr));
}
__device__ __forceinline__ void ldmx2(uint32_t* a, uint32_t addr) {
    asm volatile("ldmatrix.sync.aligned.m8n8.x2.shared.b16 {%0,%1}, [%2];"
                 : "=r"(a[0]), "=r"(a[1]) : "r"(addr));
}
__device__ __forceinline__ void mma16816(float* c, const uint32_t* a,
                                         const uint32_t* b) {
    asm volatile(
        "mma.sync.aligned.m16n8k16.row.col.f32.bf16.bf16.f32 "
        "{%0,%1,%2,%3},{%4,%5,%6,%7},{%8,%9},{%0,%1,%2,%3};"
        : "+f"(c[0]), "+f"(c[1]), "+f"(c[2]), "+f"(c[3])
        : "r"(a[0]), "r"(a[1]), "r"(a[2]), "r"(a[3]), "r"(b[0]), "r"(b[1]));
}

// ===========================================================================
// k_pre_obs_mma (bit-identical to R10)
// ===========================================================================
__global__ void __launch_bounds__(512, 1)
k_pre_obs_mma(const float* __restrict__ embed,
              const float* __restrict__ w_obs,
              const float* __restrict__ b_obs) {
    __shared__ __align__(16) __nv_bfloat16 sAhi[128 * 24];
    __shared__ __align__(16) __nv_bfloat16 sAlo[128 * 24];
    __shared__ __align__(16) __nv_bfloat16 sBhi[200 * 24];
    __shared__ __align__(16) __nv_bfloat16 sBlo[200 * 24];
    __shared__ float sbias[200];

    const int tid = threadIdx.x;
    const int wid = tid >> 5, lane = tid & 31;
    const int row0 = blockIdx.x * 128;

    const int ar = tid >> 2;
    const int akq = (tid & 3) * 4;
    const int arg = row0 + ar;
    const float* aSrc =
        embed + ((size_t)((arg & 511) * Tc + (arg >> 9))) * Ec + akq;
    int bk[7], bn[7];
#pragma unroll
    for (int j = 0; j < 7; j++) {
        int idx = tid + j * 512;
        bk[j] = idx / 200; bn[j] = idx - bk[j] * 200;
    }

    for (int i = tid; i < Hc; i += 512) sbias[i] = b_obs[i];

    const int mtile = wid >> 1;
    const int ntb = (wid & 1) * 13;
    const int ncnt = (wid & 1) ? 12 : 13;
    const uint32_t aoff =
        (uint32_t)(((mtile * 16 + (lane & 15)) * 24 + (lane >> 4) * 8) * 2);
    const uint32_t aHiAddr = smem_u32(sAhi) + aoff;
    const uint32_t aLoAddr = smem_u32(sAlo) + aoff;
    const uint32_t boff =
        (uint32_t)((((lane & 7)) * 24 + ((lane >> 3) & 1) * 8) * 2);
    const uint32_t bHiBase = smem_u32(sBhi) + boff + (uint32_t)(ntb * 8 * 48);
    const uint32_t bLoBase = smem_u32(sBlo) + boff + (uint32_t)(ntb * 8 * 48);

    float acc[13][4];
#pragma unroll
    for (int q = 0; q < 13; q++)
#pragma unroll
        for (int i = 0; i < 4; i++) acc[q][i] = 0.0f;

    float araw[4], braw[7];
    {
        float4 v = *reinterpret_cast<const float4*>(aSrc);
        araw[0] = v.x; araw[1] = v.y; araw[2] = v.z; araw[3] = v.w;
#pragma unroll
        for (int j = 0; j < 7; j++)
            if (tid + j * 512 < 3200)
                braw[j] = w_obs[(size_t)(Dc + bk[j]) * Hc + bn[j]];
    }

    for (int ck = 0; ck < 64; ck++) {
        {
            __nv_bfloat16* ah = sAhi + ar * 24 + akq;
            __nv_bfloat16* al = sAlo + ar * 24 + akq;
#pragma unroll
            for (int i = 0; i < 4; i++) {
                __nv_bfloat16 h = __float2bfloat16(araw[i]);
                ah[i] = h;
                al[i] = __float2bfloat16(araw[i] - __bfloat162float(h));
            }
#pragma unroll
            for (int j = 0; j < 7; j++) {
                if (tid + j * 512 < 3200) {
                    __nv_bfloat16 h = __float2bfloat16(braw[j]);
                    sBhi[bn[j] * 24 + bk[j]] = h;
                    sBlo[bn[j] * 24 + bk[j]] =
                        __float2bfloat16(braw[j] - __bfloat162float(h));
                }
            }
        }
        __syncthreads();

        if (ck < 63) {
            const int k0n = (ck + 1) * 16;
            float4 v = *reinterpret_cast<const float4*>(aSrc + k0n);
            araw[0] = v.x; araw[1] = v.y; araw[2] = v.z; araw[3] = v.w;
#pragma unroll
            for (int j = 0; j < 7; j++)
                if (tid + j * 512 < 3200)
                    braw[j] = w_obs[(size_t)(Dc + k0n + bk[j]) * Hc + bn[j]];
        }

        {
            uint32_t ah[4], al[4];
            ldmx4(ah, aHiAddr);
            ldmx4(al, aLoAddr);
#pragma unroll
            for (int q = 0; q < 13; q++) {
                if (q < ncnt) {
                    uint32_t bh[2], bl[2];
                    ldmx2(bh, bHiBase + (uint32_t)q * 384);
                    ldmx2(bl, bLoBase + (uint32_t)q * 384);
                    mma16816(acc[q], ah, bh);
                    mma16816(acc[q], al, bh);
                    mma16816(acc[q], ah, bl);
                }
            }
        }
        __syncthreads();
    }

    {
        const int gq = lane >> 2, t4 = lane & 3;
        const int m0 = row0 + mtile * 16 + gq;
#pragma unroll
        for (int q = 0; q < 13; q++) {
            if (q < ncnt) {
                const int n = (ntb + q) * 8 + 2 * t4;
                const float b0 = sbias[n], b1 = sbias[n + 1];
                *reinterpret_cast<float2*>(g_pre_obs + (size_t)m0 * Hc + n) =
                    make_float2(acc[q][0] + b0, acc[q][1] + b1);
                *reinterpret_cast<float2*>(g_pre_obs + (size_t)(m0 + 8) * Hc + n) =
                    make_float2(acc[q][2] + b0, acc[q][3] + b1);
            }
        }
    }
}

// ===========================================================================
// k_pre_inp_mma (NEW): g_pre_inp = [ctx||act] @ w_inp[30:292] + b_inp
// Same split-bf16 scheme; K = 262, padded to 272 = 17 chunks of 16.
// A[rg,k] = k<230 ? ctx[b,t,k] : (k<262 ? act[b,t,k-230] : 0).
// ===========================================================================
__global__ void __launch_bounds__(512, 1)
k_pre_inp_mma(const float* __restrict__ ctx,
              const float* __restrict__ actn,
              const float* __restrict__ w_inp,
              const float* __restrict__ b_inp) {
    __shared__ __align__(16) __nv_bfloat16 sAhi[128 * 24];
    __shared__ __align__(16) __nv_bfloat16 sAlo[128 * 24];
    __shared__ __align__(16) __nv_bfloat16 sBhi[200 * 24];
    __shared__ __align__(16) __nv_bfloat16 sBlo[200 * 24];
    __shared__ float sbias[200];

    const int tid = threadIdx.x;
    const int wid = tid >> 5, lane = tid & 31;
    const int row0 = blockIdx.x * 128;

    const int ar = tid >> 2;
    const int akq = (tid & 3) * 4;
    const int arg = row0 + ar;
    const int bb = arg & 511, tt = arg >> 9;
    const float* ctxRow = ctx + (size_t)(bb * Tc + tt) * SSc;
    const float* actRow = actn + (size_t)(bb * Tc + tt) * Ac;
    int bk[7], bn[7];
#pragma unroll
    for (int j = 0; j < 7; j++) {
        int idx = tid + j * 512;
        bk[j] = idx / 200; bn[j] = idx - bk[j] * 200;
    }

    for (int i = tid; i < Hc; i += 512) sbias[i] = b_inp[i];

    const int mtile = wid >> 1;
    const int ntb = (wid & 1) * 13;
    const int ncnt = (wid & 1) ? 12 : 13;
    const uint32_t aoff =
        (uint32_t)(((mtile * 16 + (lane & 15)) * 24 + (lane >> 4) * 8) * 2);
    const uint32_t aHiAddr = smem_u32(sAhi) + aoff;
    const uint32_t aLoAddr = smem_u32(sAlo) + aoff;
    const uint32_t boff =
        (uint32_t)((((lane & 7)) * 24 + ((lane >> 3) & 1) * 8) * 2);
    const uint32_t bHiBase = smem_u32(sBhi) + boff + (uint32_t)(ntb * 8 * 48);
    const uint32_t bLoBase = smem_u32(sBlo) + boff + (uint32_t)(ntb * 8 * 48);

    float acc[13][4];
#pragma unroll
    for (int q = 0; q < 13; q++)
#pragma unroll
        for (int i = 0; i < 4; i++) acc[q][i] = 0.0f;

    // prologue: load chunk 0 into regs
    float araw[4], braw[7];
#pragma unroll
    for (int i = 0; i < 4; i++) {
        int kg = akq + i;
        araw[i] = (kg < SSc) ? ctxRow[kg]
                 : (kg < SSc + Ac ? actRow[kg - SSc] : 0.0f);
    }
#pragma unroll
    for (int j = 0; j < 7; j++) {
        if (tid + j * 512 < 3200) {
            int kg = bk[j];
            braw[j] = (kg < SSc + Ac) ? w_inp[(size_t)(Sc + kg) * Hc + bn[j]]
                                      : 0.0f;
        }
    }

    for (int ck = 0; ck < 17; ck++) {
        // ---- cvt + store staged chunk ----
        {
            __nv_bfloat16* ah = sAhi + ar * 24 + akq;
            __nv_bfloat16* al = sAlo + ar * 24 + akq;
#pragma unroll
            for (int i = 0; i < 4; i++) {
                __nv_bfloat16 h = __float2bfloat16(araw[i]);
                ah[i] = h;
                al[i] = __float2bfloat16(araw[i] - __bfloat162float(h));
            }
#pragma unroll
            for (int j = 0; j < 7; j++) {
                if (tid + j * 512 < 3200) {
                    __nv_bfloat16 h = __float2bfloat16(braw[j]);
                    sBhi[bn[j] * 24 + bk[j]] = h;
                    sBlo[bn[j] * 24 + bk[j]] =
                        __float2bfloat16(braw[j] - __bfloat162float(h));
                }
            }
        }
        __syncthreads();

        // ---- prefetch next chunk (overlaps MMA below) ----
        if (ck < 16) {
            const int k0n = (ck + 1) * 16;
#pragma unroll
            for (int i = 0; i < 4; i++) {
                int kg = k0n + akq + i;
                araw[i] = (kg < SSc) ? ctxRow[kg]
                         : (kg < SSc + Ac ? actRow[kg - SSc] : 0.0f);
            }
#pragma unroll
            for (int j = 0; j < 7; j++) {
                if (tid + j * 512 < 3200) {
                    int kg = k0n + bk[j];
                    braw[j] = (kg < SSc + Ac)
                                  ? w_inp[(size_t)(Sc + kg) * Hc + bn[j]]
                                  : 0.0f;
                }
            }
        }

        // ---- ldmatrix + mma ----
        {
            uint32_t ah[4], al[4];
            ldmx4(ah, aHiAddr);
            ldmx4(al, aLoAddr);
#pragma unroll
            for (int q = 0; q < 13; q++) {
                if (q < ncnt) {
                    uint32_t bh[2], bl[2];
                    ldmx2(bh, bHiBase + (uint32_t)q * 384);
                    ldmx2(bl, bLoBase + (uint32_t)q * 384);
                    mma16816(acc[q], ah, bh);
                    mma16816(acc[q], al, bh);
                    mma16816(acc[q], ah, bl);
                }
            }
        }
        __syncthreads();
    }

    // ---- epilogue ----
    {
        const int gq = lane >> 2, t4 = lane & 3;
        const int m0 = row0 + mtile * 16 + gq;
#pragma unroll
        for (int q = 0; q < 13; q++) {
            if (q < ncnt) {
                const int n = (ntb + q) * 8 + 2 * t4;
                const float b0 = sbias[n], b1 = sbias[n + 1];
                *reinterpret_cast<float2*>(g_pre_inp + (size_t)m0 * Hc + n) =
                    make_float2(acc[q][0] + b0, acc[q][1] + b1);
                *reinterpret_cast<float2*>(g_pre_inp + (size_t)(m0 + 8) * Hc + n) =
                    make_float2(acc[q][2] + b0, acc[q][3] + b1);
            }
        }
    }
}

// ===========================================================================
// k_rssm — exact R6/R10 v4 (proven best scan)
// ===========================================================================
#define XD_OFF   0
#define DN_OFF   25600
#define HHO_OFF  38400
#define PART_OFF 64000
#define STS_OFF  104800
#define SOS_OFF  106848
#define STF_OFF  108896
#define BGRU_OFF 109920
#define BIMG_OFF 112320
#define BIMS_OFF 113120
#define BOBS_OFF 113376
#define SMEM_BYTES 113632

__global__ void __launch_bounds__(640, 1) __cluster_dims__(2, 1, 1) k_rssm(
    const float* __restrict__ noise_p, const float* __restrict__ noise_o,
    const float* __restrict__ w_inp,  const float* __restrict__ w_gru,
    const float* __restrict__ b_gru_g,
    const float* __restrict__ w_img,  const float* __restrict__ b_img_g,
    const float* __restrict__ w_obsd,
    const float* __restrict__ w_ims,  const float* __restrict__ b_ims_g,
    const float* __restrict__ w_obst, const float* __restrict__ b_obst_g,
    float* __restrict__ out) {
    extern __shared__ __align__(16) char sm[];
    ull*   xd_u   = reinterpret_cast<ull*>(sm + XD_OFF);
    ull*   dn_u   = reinterpret_cast<ull*>(sm + DN_OFF);
    ull*   hho_u  = reinterpret_cast<ull*>(sm + HHO_OFF);
    ull*   part_u = reinterpret_cast<ull*>(sm + PART_OFF);
    float* part_f = reinterpret_cast<float*>(sm + PART_OFF);
    float* stS    = reinterpret_cast<float*>(sm + STS_OFF);
    float* soS    = reinterpret_cast<float*>(sm + SOS_OFF);
    float* st_f   = reinterpret_cast<float*>(sm + STF_OFF);
    float* bgru   = reinterpret_cast<float*>(sm + BGRU_OFF);
    float* bimg   = reinterpret_cast<float*>(sm + BIMG_OFF);
    float* bims   = reinterpret_cast<float*>(sm + BIMS_OFF);
    float* bobs   = reinterpret_cast<float*>(sm + BOBS_OFF);
    const ulonglong2* xd_u2 = reinterpret_cast<const ulonglong2*>(xd_u);
    const ulonglong2* dn_u2 = reinterpret_cast<const ulonglong2*>(dn_u);
    const ulonglong2* hho_u2 = reinterpret_cast<const ulonglong2*>(hho_u);
    const float* xd_f = reinterpret_cast<const float*>(xd_u);
    const float* dn_f = reinterpret_cast<const float*>(dn_u);

    const int tid = threadIdx.x;
    const uint32_t p = ctarank();
    const uint32_t peer = 1u - p;
    const int b0 = (blockIdx.x >> 1) * 8;
    const uint32_t base32 = smem_u32(sm);

    for (int i = tid; i < 600; i += 640) bgru[i] = b_gru_g[i];
    for (int i = tid; i < Hc; i += 640) bimg[i] = b_img_g[i];
    if (tid < 60) { bims[tid] = b_ims_g[tid]; bobs[tid] = b_obst_g[tid]; }
    for (int i = tid; i < 1600; i += 640) xd_u[1600 + i] = 0ull;
    for (int i = tid; i < 256; i += 640) st_f[i] = 0.0f;
    __syncthreads();
    CB();

    for (int t = 0; t < Tc; t++) {
        if (tid < 400) {
            const int j = tid >> 1, rh = tid & 1;
            const float* pi = g_pre_inp + ((size_t)t * Bc + b0) * Hc + j;
            float a0 = pi[(rh * 4 + 0) * Hc], a1 = pi[(rh * 4 + 1) * Hc];
            float a2 = pi[(rh * 4 + 2) * Hc], a3 = pi[(rh * 4 + 3) * Hc];
#pragma unroll
            for (int k = 0; k < Sc; k++) {
                float w = w_inp[k * Hc + j];
                float4 s = *reinterpret_cast<const float4*>(&st_f[k * 8 + rh * 4]);
                a0 = fmaf(w, s.x, a0); a1 = fmaf(w, s.y, a1);
                a2 = fmaf(w, s.z, a2); a3 = fmaf(w, s.w, a3);
            }
            ull* xo = &xd_u[j * 8 + rh * 4];
            xo[0] = dup2(eluf(a0)); xo[1] = dup2(eluf(a1));
            xo[2] = dup2(eluf(a2)); xo[3] = dup2(eluf(a3));
        }
        __syncthreads();

        if (tid < 600) {
            const int cg = tid % 75;
            const int z = tid / 75;
            const int rh = z & 1, seg = z >> 1;
            const int lc0 = cg * 4;
            const int gcol0 = (lc0 / 100) * 200 + (int)p * 100 + (lc0 % 100);
            const ulonglong2* Wp = reinterpret_cast<const ulonglong2*>(w_gru + gcol0)
                                   + (size_t)seg * 100 * 150;
            const ulonglong2* Ap = xd_u2 + (seg * 100) * 4 + rh * 2;
            ull A0 = 0, A1 = 0, A2 = 0, A3 = 0, A4 = 0, A5 = 0, A6 = 0, A7 = 0;
#pragma unroll 4
            for (int kk = 0; kk < 100; kk++) {
                ulonglong2 w = Wp[(size_t)kk * 150];
                ulonglong2 a01 = Ap[kk * 4];
                ulonglong2 a23 = Ap[kk * 4 + 1];
                fma2(A0, w.x, a01.x); fma2(A1, w.y, a01.x);
                fma2(A2, w.x, a01.y); fma2(A3, w.y, a01.y);
                fma2(A4, w.x, a23.x); fma2(A5, w.y, a23.x);
                fma2(A6, w.x, a23.y); fma2(A7, w.y, a23.y);
            }
            ull* P = part_u + (seg * 75 + cg) * 17 + rh * 4;
            P[0] = A0; P[8] = A1; P[1] = A2; P[9] = A3;
            P[2] = A4; P[10] = A5; P[3] = A6; P[11] = A7;
        }
        __syncthreads();

        if (tid < 400) {
            const int j = tid >> 2, q = tid & 3;
            const int gd = (int)p * 100 + j;
            const int jq = j >> 2, ci = j & 3, cp = ci >> 1, e = ci & 1;
            const float bR = bgru[gd], bC = bgru[200 + gd], bU = bgru[400 + gd];
#pragma unroll
            for (int w2 = 0; w2 < 2; w2++) {
                const int rr = q * 2 + w2;
                float R = bR, C = bC, U = bU - 1.0f;
#pragma unroll
                for (int seg = 0; seg < 4; seg++) {
                    R += part_f[(((seg * 75 + 0 * 25 + jq) * 17 + cp * 8 + rr) << 1) + e];
                    C += part_f[(((seg * 75 + 1 * 25 + jq) * 17 + cp * 8 + rr) << 1) + e];
                    U += part_f[(((seg * 75 + 2 * 25 + jq) * 17 + cp * 8 + rr) << 1) + e];
                }
                float reset = sigm(R);
                float cand  = tanhf(reset * C);
                float upd   = sigm(U);
                float dprev = xd_f[((200 + gd) * 8 + rr) * 2];
                float dnv = upd * cand + (1.0f - upd) * dprev;
                ull dv = dup2(dnv);
                dn_u[gd * 8 + rr] = dv;
                st_peer_u64(base32 + DN_OFF + (uint32_t)(gd * 8 + rr) * 8, peer, dv);
            }
        }
        CB();

        if (tid < 400) {
            const int grp = tid % 50;
            const int z = tid / 50;
            const int rh = z & 1, seg = z >> 1;
            const float* W = (grp < 25)
                ? (w_img + (int)p * 100 + grp * 4)
                : (w_obsd + (int)p * 100 + (grp - 25) * 4);
            const ulonglong2* Wp = reinterpret_cast<const ulonglong2*>(W)
                                   + (size_t)(seg * 50) * 50;
            const ulonglong2* Ap = dn_u2 + (seg * 50) * 4 + rh * 2;
            ull A0 = 0, A1 = 0, A2 = 0, A3 = 0, A4 = 0, A5 = 0, A6 = 0, A7 = 0;
#pragma unroll 5
            for (int kk = 0; kk < 50; kk++) {
                ulonglong2 w = Wp[(size_t)kk * 50];
                ulonglong2 a01 = Ap[kk * 4];
                ulonglong2 a23 = Ap[kk * 4 + 1];
                fma2(A0, w.x, a01.x); fma2(A1, w.y, a01.x);
                fma2(A2, w.x, a01.y); fma2(A3, w.y, a01.y);
                fma2(A4, w.x, a23.x); fma2(A5, w.y, a23.x);
                fma2(A6, w.x, a23.y); fma2(A7, w.y, a23.y);
            }
            ull* P = part_u + (seg * 50 + grp) * 17 + rh * 4;
            P[0] = A0; P[8] = A1; P[1] = A2; P[9] = A3;
            P[2] = A4; P[10] = A5; P[3] = A6; P[11] = A7;
        } else {
            const int tt2 = tid - 400;
            for (int i = tt2; i < 800; i += 240) {
                const int rl = i / 200, j = i % 200;
                const int r = (int)p * 4 + rl;
                out[((size_t)(b0 + r) * Tc + t) * OUTC + 180 + j] =
                    dn_f[(j * 8 + r) * 2];
            }
            for (int i = tt2; i < 1600; i += 240) xd_u[1600 + i] = dn_u[i];
        }
        __syncthreads();

        if (tid < 400) {
            const int cl = tid >> 1;
            const int rh = (tid & 1) * 4;
            const bool ish = cl < 100;
            const int gcol = (int)p * 100 + (ish ? cl : cl - 100);
            const int grp = ish ? (cl >> 2) : (25 + ((cl - 100) >> 2));
            const int ci = cl & 3, cp = ci >> 1, e = ci & 1;
            const float* po = g_pre_obs + ((size_t)t * Bc + b0) * Hc + gcol;
            const float bb = ish ? bimg[gcol] : 0.0f;
            const int dsti = ish ? gcol : 200 + gcol;
#pragma unroll
            for (int i = 0; i < 4; i++) {
                const int r = rh + i;
                float v = ish ? bb : po[r * Hc];
#pragma unroll
                for (int seg = 0; seg < 4; seg++)
                    v += part_f[(((seg * 50 + grp) * 17 + cp * 8 + r) << 1) + e];
                ull dv = dup2(eluf(v));
                hho_u[dsti * 8 + r] = dv;
                st_peer_u64(base32 + HHO_OFF + (uint32_t)(dsti * 8 + r) * 8, peer, dv);
            }
        }
        CB();

        if (tid < 240) {
            const int grp = tid % 15;
            const int z = tid / 15;
            const int rh = z & 1, seg = z >> 1;
            const float* W = (p ? w_obst : w_ims) + grp * 4;
            const ulonglong2* Wp = reinterpret_cast<const ulonglong2*>(W)
                                   + (size_t)(seg * 25) * 15;
            const ulonglong2* Ap = hho_u2 + (int)p * 800 + (seg * 25) * 4 + rh * 2;
            ull A0 = 0, A1 = 0, A2 = 0, A3 = 0, A4 = 0, A5 = 0, A6 = 0, A7 = 0;
#pragma unroll 5
            for (int kk = 0; kk < 25; kk++) {
                ulonglong2 w = Wp[(size_t)kk * 15];
                ulonglong2 a01 = Ap[kk * 4];
                ulonglong2 a23 = Ap[kk * 4 + 1];
                fma2(A0, w.x, a01.x); fma2(A1, w.y, a01.x);
                fma2(A2, w.x, a01.y); fma2(A3, w.y, a01.y);
                fma2(A4, w.x, a23.x); fma2(A5, w.y, a23.x);
                fma2(A6, w.x, a23.y); fma2(A7, w.y, a23.y);
            }
            ull* P = part_u + (seg * 15 + grp) * 17 + rh * 4;
            P[0] = A0; P[8] = A1; P[1] = A2; P[9] = A3;
            P[2] = A4; P[10] = A5; P[3] = A6; P[11] = A7;
        }
        __syncthreads();

        if (tid < 240) {
            const int col = tid >> 2, q = tid & 3;
            const int cgq = col >> 2, ci = col & 3, cp = ci >> 1, e = ci & 1;
            const float bb = p ? bobs[col] : bims[col];
            const uint32_t dstoff = p ? SOS_OFF : STS_OFF;
            float* dst = reinterpret_cast<float*>(sm + dstoff);
#pragma unroll
            for (int w2 = 0; w2 < 2; w2++) {
                const int rr = q * 2 + w2;
                float v = bb;
#pragma unroll
                for (int seg = 0; seg < 8; seg++)
                    v += part_f[(((seg * 15 + cgq) * 17 + cp * 8 + rr) << 1) + e];
                dst[rr * 64 + col] = v;
                st_peer_f32(base32 + dstoff + (uint32_t)(rr * 64 + col) * 4, peer, v);
            }
        }
        CB();

        if (tid < 240) {
            const int r = tid / 30, k = tid - r * 30;
            const int b = b0 + r;
            float om  = soS[r * 64 + k];
            float osv = softplusf(soS[r * 64 + 30 + k]) + 0.1f;
            float ost = fmaf(osv, noise_o[((size_t)t * Bc + b) * Sc + k], om);
            st_f[k * 8 + r] = ost;
            if ((r >> 2) == (int)p) {
                float pm  = stS[r * 64 + k];
                float psv = softplusf(stS[r * 64 + 30 + k]) + 0.1f;
                float pst = fmaf(psv, noise_p[((size_t)t * Bc + b) * Sc + k], pm);
                size_t basep = ((size_t)b * Tc + t) * OUTC;
                out[basep + k]       = om;
                out[basep + 30 + k]  = osv;
                out[basep + 60 + k]  = ost;
                out[basep + 90 + k]  = pm;
                out[basep + 120 + k] = psv;
                out[basep + 150 + k] = pst;
            }
        }
        __syncthreads();
    }
}

// ===========================================================================
extern "C" void kernel_launch(void* const* d_in, const int* in_sizes, int n_in,
                              void* d_out, int out_size) {
    const float* embed       = (const float*)d_in[0];
    const float* action      = (const float*)d_in[1];
    const float* context     = (const float*)d_in[2];
    const float* noise_prior = (const float*)d_in[3];
    const float* noise_post  = (const float*)d_in[4];
    const float* w_inp       = (const float*)d_in[5];
    const float* b_inp       = (const float*)d_in[6];
    const float* w_gru       = (const float*)d_in[7];
    const float* b_gru       = (const float*)d_in[8];
    const float* w_img_out   = (const float*)d_in[9];
    const float* b_img_out   = (const float*)d_in[10];
    const float* w_obs_out   = (const float*)d_in[11];
    const float* b_obs_out   = (const float*)d_in[12];
    const float* w_ims_stat  = (const float*)d_in[13];
    const float* b_ims_stat  = (const float*)d_in[14];
    const float* w_obs_stat  = (const float*)d_in[15];
    const float* b_obs_stat  = (const float*)d_in[16];
    float* out = (float*)d_out;

    static int smem_set = 0;
    if (!smem_set) {
        cudaFuncSetAttribute(k_rssm, cudaFuncAttributeMaxDynamicSharedMemorySize,
                             SMEM_BYTES);
        smem_set = 1;
    }

    k_pre_inp_mma<<<Bc * Tc / 128, 512>>>(context, action, w_inp, b_inp);
    k_pre_obs_mma<<<Bc * Tc / 128, 512>>>(embed, w_obs_out, b_obs_out);
    k_rssm<<<128, 640, SMEM_BYTES>>>(noise_prior, noise_post, w_inp, w_gru,
                                     b_gru, w_img_out, b_img_out, w_obs_out,
                                     w_ims_stat, b_ims_stat, w_obs_stat,
                                     b_obs_stat, out);
}

// round 13
// speedup vs baseline: 1.2426x; 1.0040x over previous
#include <cuda_runtime.h>
#include <cuda_bf16.h>
#include <cstdint>

// ---------------------------------------------------------------------------
// RSSM observe scan, GB300 — round 13.
//   k_pre  : obs + inp split-bf16 mma GEMMs merged into ONE 512-CTA launch.
//   k_rssm : R6 v4 scan with barrier.cluster (L1D-flushing, ~490cyc) replaced
//            by DSMEM mbarrier release/acquire exchanges (R8-proven protocol).
//            L1D now persists across steps -> weight reads can hit L1.
// ---------------------------------------------------------------------------

#define Bc 512
#define Tc 64
#define Ec 1024
#define Ac 32
#define Sc 30
#define Dc 200
#define Hc 200
#define SSc 230
#define OUTC 380

typedef unsigned long long ull;

__device__ float g_pre_inp[Tc * Bc * Hc];
__device__ float g_pre_obs[Tc * Bc * Hc];

// ---- packed f32x2 helpers -------------------------------------------------
__device__ __forceinline__ ull pk2(float a, float b) {
    ull r; asm("mov.b64 %0, {%1, %2};" : "=l"(r) : "f"(a), "f"(b)); return r;
}
__device__ __forceinline__ ull dup2(float a) {
    ull r; asm("mov.b64 %0, {%1, %1};" : "=l"(r) : "f"(a)); return r;
}
__device__ __forceinline__ float2 up2(ull v) {
    float x, y; asm("mov.b64 {%0, %1}, %2;" : "=f"(x), "=f"(y) : "l"(v));
    return make_float2(x, y);
}
__device__ __forceinline__ void fma2(ull& acc, ull a, ull b) {
    asm("fma.rn.f32x2 %0, %1, %2, %0;" : "+l"(acc) : "l"(a), "l"(b));
}

__device__ __forceinline__ float sigm(float x) { return 1.0f / (1.0f + __expf(-x)); }
__device__ __forceinline__ float eluf(float x) { return x > 0.0f ? x : (__expf(x) - 1.0f); }
__device__ __forceinline__ float softplusf(float x) {
    return x > 15.0f ? x : log1pf(__expf(x));
}

// ---- cluster / smem helpers -------------------------------------------------
__device__ __forceinline__ uint32_t smem_u32(const void* p) {
    uint32_t a;
    asm("{ .reg .u64 t; cvta.to.shared.u64 t, %1; cvt.u32.u64 %0, t; }"
        : "=r"(a) : "l"(p));
    return a;
}
__device__ __forceinline__ void st_peer_u64(uint32_t laddr, uint32_t rank, ull v) {
    uint32_t ra;
    asm volatile("mapa.shared::cluster.u32 %0, %1, %2;" : "=r"(ra)
                 : "r"(laddr), "r"(rank));
    asm volatile("st.shared::cluster.u64 [%0], %1;" :: "r"(ra), "l"(v) : "memory");
}
__device__ __forceinline__ void st_peer_f32(uint32_t laddr, uint32_t rank, float v) {
    uint32_t ra;
    asm volatile("mapa.shared::cluster.u32 %0, %1, %2;" : "=r"(ra)
                 : "r"(laddr), "r"(rank));
    asm volatile("st.shared::cluster.f32 [%0], %1;" :: "r"(ra), "f"(v) : "memory");
}
__device__ __forceinline__ uint32_t ctarank() {
    uint32_t r; asm("mov.u32 %0, %%cluster_ctarank;" : "=r"(r)); return r;
}
__device__ __forceinline__ void mbar_init(uint32_t addr, uint32_t cnt) {
    asm volatile("mbarrier.init.shared.b64 [%0], %1;" :: "r"(addr), "r"(cnt)
                 : "memory");
}
__device__ __forceinline__ void mbar_arrive_peer(uint32_t laddr, uint32_t rank) {
    uint32_t ra;
    asm volatile("mapa.shared::cluster.u32 %0, %1, %2;" : "=r"(ra)
                 : "r"(laddr), "r"(rank));
    asm volatile("mbarrier.arrive.release.cluster.shared::cluster.b64 _, [%0];"
                 :: "r"(ra) : "memory");
}
__device__ __forceinline__ void mbar_wait(uint32_t addr, uint32_t parity) {
    asm volatile(
        "{\n\t.reg .pred P;\n\t"
        "W%=:\n\t"
        "mbarrier.try_wait.parity.acquire.cluster.shared::cta.b64 P, [%0], %1, 0x989680;\n\t"
        "@P bra D%=;\n\t"
        "bra W%=;\n\t"
        "D%=:\n\t}"
        :: "r"(addr), "r"(parity) : "memory");
}
#define CB() do { asm volatile("barrier.cluster.arrive.aligned;" ::: "memory"); \
                  asm volatile("barrier.cluster.wait.aligned;" ::: "memory"); } while (0)

// ---- mma.sync helpers (compute_103-legal) -----------------------------------
__device__ __forceinline__ void ldmx4(uint32_t* a, uint32_t addr) {
    asm volatile("ldmatrix.sync.aligned.m8n8.x4.shared.b16 {%0,%1,%2,%3}, [%4];"
                 : "=r"(a[0]), "=r"(a[1]), "=r"(a[2]), "=r"(a[3]) : "r"(addr));
}
__device__ __forceinline__ void ldmx2(uint32_t* a, uint32_t addr) {
    asm volatile("ldmatrix.sync.aligned.m8n8.x2.shared.b16 {%0,%1}, [%2];"
                 : "=r"(a[0]), "=r"(a[1]) : "r"(addr));
}
__device__ __forceinline__ void mma16816(float* c, const uint32_t* a,
                                         const uint32_t* b) {
    asm volatile(
        "mma.sync.aligned.m16n8k16.row.col.f32.bf16.bf16.f32 "
        "{%0,%1,%2,%3},{%4,%5,%6,%7},{%8,%9},{%0,%1,%2,%3};"
        : "+f"(c[0]), "+f"(c[1]), "+f"(c[2]), "+f"(c[3])
        : "r"(a[0]), "r"(a[1]), "r"(a[2]), "r"(a[3]), "r"(b[0]), "r"(b[1]));
}

// ===========================================================================
// k_pre: merged pre GEMMs. blocks [0,256): pre_obs (K=1024, 64 chunks);
// blocks [256,512): pre_inp (K=262 pad 272, 17 chunks). Bodies identical to
// the R10/R12-proven kernels.
// ===========================================================================
__global__ void __launch_bounds__(512, 1)
k_pre(const float* __restrict__ embed,
      const float* __restrict__ ctx,
      const float* __restrict__ actn,
      const float* __restrict__ w_obs,
      const float* __restrict__ b_obs,
      const float* __restrict__ w_inp,
      const float* __restrict__ b_inp) {
    __shared__ __align__(16) __nv_bfloat16 sAhi[128 * 24];
    __shared__ __align__(16) __nv_bfloat16 sAlo[128 * 24];
    __shared__ __align__(16) __nv_bfloat16 sBhi[200 * 24];
    __shared__ __align__(16) __nv_bfloat16 sBlo[200 * 24];
    __shared__ float sbias[200];

    const int tid = threadIdx.x;
    const int wid = tid >> 5, lane = tid & 31;
    const bool is_obs = blockIdx.x < 256;
    const int row0 = (is_obs ? blockIdx.x : blockIdx.x - 256) * 128;

    const int ar = tid >> 2;
    const int akq = (tid & 3) * 4;
    const int arg = row0 + ar;
    const int bb = arg & 511, tt = arg >> 9;
    int bk[7], bn[7];
#pragma unroll
    for (int j = 0; j < 7; j++) {
        int idx = tid + j * 512;
        bk[j] = idx / 200; bn[j] = idx - bk[j] * 200;
    }

    for (int i = tid; i < Hc; i += 512) sbias[i] = is_obs ? b_obs[i] : b_inp[i];

    const int mtile = wid >> 1;
    const int ntb = (wid & 1) * 13;
    const int ncnt = (wid & 1) ? 12 : 13;
    const uint32_t aoff =
        (uint32_t)(((mtile * 16 + (lane & 15)) * 24 + (lane >> 4) * 8) * 2);
    const uint32_t aHiAddr = smem_u32(sAhi) + aoff;
    const uint32_t aLoAddr = smem_u32(sAlo) + aoff;
    const uint32_t boff =
        (uint32_t)((((lane & 7)) * 24 + ((lane >> 3) & 1) * 8) * 2);
    const uint32_t bHiBase = smem_u32(sBhi) + boff + (uint32_t)(ntb * 8 * 48);
    const uint32_t bLoBase = smem_u32(sBlo) + boff + (uint32_t)(ntb * 8 * 48);

    float acc[13][4];
#pragma unroll
    for (int q = 0; q < 13; q++)
#pragma unroll
        for (int i = 0; i < 4; i++) acc[q][i] = 0.0f;

    const float* aSrcObs = embed + ((size_t)(bb * Tc + tt)) * Ec + akq;
    const float* ctxRow = ctx + (size_t)(bb * Tc + tt) * SSc;
    const float* actRow = actn + (size_t)(bb * Tc + tt) * Ac;

    const int nck = is_obs ? 64 : 17;
    float araw[4], braw[7];
    // prologue: chunk 0
    if (is_obs) {
        float4 v = *reinterpret_cast<const float4*>(aSrcObs);
        araw[0] = v.x; araw[1] = v.y; araw[2] = v.z; araw[3] = v.w;
#pragma unroll
        for (int j = 0; j < 7; j++)
            if (tid + j * 512 < 3200)
                braw[j] = w_obs[(size_t)(Dc + bk[j]) * Hc + bn[j]];
    } else {
#pragma unroll
        for (int i = 0; i < 4; i++) {
            int kg = akq + i;
            araw[i] = (kg < SSc) ? ctxRow[kg]
                     : (kg < SSc + Ac ? actRow[kg - SSc] : 0.0f);
        }
#pragma unroll
        for (int j = 0; j < 7; j++) {
            if (tid + j * 512 < 3200) {
                int kg = bk[j];
                braw[j] = (kg < SSc + Ac) ? w_inp[(size_t)(Sc + kg) * Hc + bn[j]]
                                          : 0.0f;
            }
        }
    }

    for (int ck = 0; ck < nck; ck++) {
        // ---- cvt + store staged chunk ----
        {
            __nv_bfloat16* ah = sAhi + ar * 24 + akq;
            __nv_bfloat16* al = sAlo + ar * 24 + akq;
#pragma unroll
            for (int i = 0; i < 4; i++) {
                __nv_bfloat16 h = __float2bfloat16(araw[i]);
                ah[i] = h;
                al[i] = __float2bfloat16(araw[i] - __bfloat162float(h));
            }
#pragma unroll
            for (int j = 0; j < 7; j++) {
                if (tid + j * 512 < 3200) {
                    __nv_bfloat16 h = __float2bfloat16(braw[j]);
                    sBhi[bn[j] * 24 + bk[j]] = h;
                    sBlo[bn[j] * 24 + bk[j]] =
                        __float2bfloat16(braw[j] - __bfloat162float(h));
                }
            }
        }
        __syncthreads();

        // ---- prefetch next chunk (overlaps MMA below) ----
        if (ck + 1 < nck) {
            const int k0n = (ck + 1) * 16;
            if (is_obs) {
                float4 v = *reinterpret_cast<const float4*>(aSrcObs + k0n);
                araw[0] = v.x; araw[1] = v.y; araw[2] = v.z; araw[3] = v.w;
#pragma unroll
                for (int j = 0; j < 7; j++)
                    if (tid + j * 512 < 3200)
                        braw[j] = w_obs[(size_t)(Dc + k0n + bk[j]) * Hc + bn[j]];
            } else {
#pragma unroll
                for (int i = 0; i < 4; i++) {
                    int kg = k0n + akq + i;
                    araw[i] = (kg < SSc) ? ctxRow[kg]
                             : (kg < SSc + Ac ? actRow[kg - SSc] : 0.0f);
                }
#pragma unroll
                for (int j = 0; j < 7; j++) {
                    if (tid + j * 512 < 3200) {
                        int kg = k0n + bk[j];
                        braw[j] = (kg < SSc + Ac)
                                      ? w_inp[(size_t)(Sc + kg) * Hc + bn[j]]
                                      : 0.0f;
                    }
                }
            }
        }

        // ---- ldmatrix + mma ----
        {
            uint32_t ah[4], al[4];
            ldmx4(ah, aHiAddr);
            ldmx4(al, aLoAddr);
#pragma unroll
            for (int q = 0; q < 13; q++) {
                if (q < ncnt) {
                    uint32_t bh[2], bl[2];
                    ldmx2(bh, bHiBase + (uint32_t)q * 384);
                    ldmx2(bl, bLoBase + (uint32_t)q * 384);
                    mma16816(acc[q], ah, bh);
                    mma16816(acc[q], al, bh);
                    mma16816(acc[q], ah, bl);
                }
            }
        }
        __syncthreads();
    }

    // ---- epilogue ----
    {
        float* gdst = is_obs ? g_pre_obs : g_pre_inp;
        const int gq = lane >> 2, t4 = lane & 3;
        const int m0 = row0 + mtile * 16 + gq;
#pragma unroll
        for (int q = 0; q < 13; q++) {
            if (q < ncnt) {
                const int n = (ntb + q) * 8 + 2 * t4;
                const float b0 = sbias[n], b1 = sbias[n + 1];
                *reinterpret_cast<float2*>(gdst + (size_t)m0 * Hc + n) =
                    make_float2(acc[q][0] + b0, acc[q][1] + b1);
                *reinterpret_cast<float2*>(gdst + (size_t)(m0 + 8) * Hc + n) =
                    make_float2(acc[q][2] + b0, acc[q][3] + b1);
            }
        }
    }
}

// ===========================================================================
// k_rssm — R6 v4 structure; cluster barriers replaced by DSMEM mbarrier
// release/acquire exchanges (no L1D flush, no ~490cyc UCGABAR_WAIT).
// ===========================================================================
#define XD_OFF   0
#define DN_OFF   25600
#define HHO_OFF  38400
#define PART_OFF 64000
#define STS_OFF  104800
#define SOS_OFF  106848
#define STF_OFF  108896
#define BGRU_OFF 109920
#define BIMG_OFF 112320
#define BIMS_OFF 113120
#define BOBS_OFF 113376
#define MBAR_OFF 113632
#define SMEM_BYTES 113656

__global__ void __launch_bounds__(640, 1) __cluster_dims__(2, 1, 1) k_rssm(
    const float* __restrict__ noise_p, const float* __restrict__ noise_o,
    const float* __restrict__ w_inp,  const float* __restrict__ w_gru,
    const float* __restrict__ b_gru_g,
    const float* __restrict__ w_img,  const float* __restrict__ b_img_g,
    const float* __restrict__ w_obsd,
    const float* __restrict__ w_ims,  const float* __restrict__ b_ims_g,
    const float* __restrict__ w_obst, const float* __restrict__ b_obst_g,
    float* __restrict__ out) {
    extern __shared__ __align__(16) char sm[];
    ull*   xd_u   = reinterpret_cast<ull*>(sm + XD_OFF);
    ull*   dn_u   = reinterpret_cast<ull*>(sm + DN_OFF);
    ull*   hho_u  = reinterpret_cast<ull*>(sm + HHO_OFF);
    ull*   part_u = reinterpret_cast<ull*>(sm + PART_OFF);
    float* part_f = reinterpret_cast<float*>(sm + PART_OFF);
    float* stS    = reinterpret_cast<float*>(sm + STS_OFF);
    float* soS    = reinterpret_cast<float*>(sm + SOS_OFF);
    float* st_f   = reinterpret_cast<float*>(sm + STF_OFF);
    float* bgru   = reinterpret_cast<float*>(sm + BGRU_OFF);
    float* bimg   = reinterpret_cast<float*>(sm + BIMG_OFF);
    float* bims   = reinterpret_cast<float*>(sm + BIMS_OFF);
    float* bobs   = reinterpret_cast<float*>(sm + BOBS_OFF);
    const ulonglong2* xd_u2 = reinterpret_cast<const ulonglong2*>(xd_u);
    const ulonglong2* dn_u2 = reinterpret_cast<const ulonglong2*>(dn_u);
    const ulonglong2* hho_u2 = reinterpret_cast<const ulonglong2*>(hho_u);
    const float* xd_f = reinterpret_cast<const float*>(xd_u);
    const float* dn_f = reinterpret_cast<const float*>(dn_u);

    const int tid = threadIdx.x;
    const uint32_t p = ctarank();
    const uint32_t peer = 1u - p;
    const int b0 = (blockIdx.x >> 1) * 8;
    const uint32_t base32 = smem_u32(sm);
    const uint32_t mb_dn  = base32 + MBAR_OFF;
    const uint32_t mb_hho = base32 + MBAR_OFF + 8;
    const uint32_t mb_st  = base32 + MBAR_OFF + 16;

    for (int i = tid; i < 600; i += 640) bgru[i] = b_gru_g[i];
    for (int i = tid; i < Hc; i += 640) bimg[i] = b_img_g[i];
    if (tid < 60) { bims[tid] = b_ims_g[tid]; bobs[tid] = b_obst_g[tid]; }
    for (int i = tid; i < 1600; i += 640) xd_u[1600 + i] = 0ull;
    for (int i = tid; i < 256; i += 640) st_f[i] = 0.0f;
    if (tid == 0) {
        mbar_init(mb_dn, 400);
        mbar_init(mb_hho, 400);
        mbar_init(mb_st, 240);
    }
    __syncthreads();
    CB();   // once: peer mbarrier init visible before any arrive

    uint32_t ph = 0;
    for (int t = 0; t < Tc; t++) {
        // ---- P1: x = elu(stoch @ Wis + pre_inp[t]) ----
        if (tid < 400) {
            const int j = tid >> 1, rh = tid & 1;
            const float* pi = g_pre_inp + ((size_t)t * Bc + b0) * Hc + j;
            float a0 = pi[(rh * 4 + 0) * Hc], a1 = pi[(rh * 4 + 1) * Hc];
            float a2 = pi[(rh * 4 + 2) * Hc], a3 = pi[(rh * 4 + 3) * Hc];
#pragma unroll
            for (int k = 0; k < Sc; k++) {
                float w = w_inp[k * Hc + j];
                float4 s = *reinterpret_cast<const float4*>(&st_f[k * 8 + rh * 4]);
                a0 = fmaf(w, s.x, a0); a1 = fmaf(w, s.y, a1);
                a2 = fmaf(w, s.z, a2); a3 = fmaf(w, s.w, a3);
            }
            ull* xo = &xd_u[j * 8 + rh * 4];
            xo[0] = dup2(eluf(a0)); xo[1] = dup2(eluf(a1));
            xo[2] = dup2(eluf(a2)); xo[3] = dup2(eluf(a3));
        }
        __syncthreads();

        // ---- P2: GRU partials (our 300 gate-cols, k-split 4) ----
        if (tid < 600) {
            const int cg = tid % 75;
            const int z = tid / 75;
            const int rh = z & 1, seg = z >> 1;
            const int lc0 = cg * 4;
            const int gcol0 = (lc0 / 100) * 200 + (int)p * 100 + (lc0 % 100);
            const ulonglong2* Wp = reinterpret_cast<const ulonglong2*>(w_gru + gcol0)
                                   + (size_t)seg * 100 * 150;
            const ulonglong2* Ap = xd_u2 + (seg * 100) * 4 + rh * 2;
            ull A0 = 0, A1 = 0, A2 = 0, A3 = 0, A4 = 0, A5 = 0, A6 = 0, A7 = 0;
#pragma unroll 4
            for (int kk = 0; kk < 100; kk++) {
                ulonglong2 w = Wp[(size_t)kk * 150];
                ulonglong2 a01 = Ap[kk * 4];
                ulonglong2 a23 = Ap[kk * 4 + 1];
                fma2(A0, w.x, a01.x); fma2(A1, w.y, a01.x);
                fma2(A2, w.x, a01.y); fma2(A3, w.y, a01.y);
                fma2(A4, w.x, a23.x); fma2(A5, w.y, a23.x);
                fma2(A6, w.x, a23.y); fma2(A7, w.y, a23.y);
            }
            ull* P = part_u + (seg * 75 + cg) * 17 + rh * 4;
            P[0] = A0; P[8] = A1; P[1] = A2; P[9] = A3;
            P[2] = A4; P[10] = A5; P[3] = A6; P[11] = A7;
        }
        __syncthreads();

        // ---- C2: gates -> deter_new (our 100 cols); dup local + peer ----
        if (tid < 400) {
            const int j = tid >> 2, q = tid & 3;
            const int gd = (int)p * 100 + j;
            const int jq = j >> 2, ci = j & 3, cp = ci >> 1, e = ci & 1;
            const float bR = bgru[gd], bC = bgru[200 + gd], bU = bgru[400 + gd];
#pragma unroll
            for (int w2 = 0; w2 < 2; w2++) {
                const int rr = q * 2 + w2;
                float R = bR, C = bC, U = bU - 1.0f;
#pragma unroll
                for (int seg = 0; seg < 4; seg++) {
                    R += part_f[(((seg * 75 + 0 * 25 + jq) * 17 + cp * 8 + rr) << 1) + e];
                    C += part_f[(((seg * 75 + 1 * 25 + jq) * 17 + cp * 8 + rr) << 1) + e];
                    U += part_f[(((seg * 75 + 2 * 25 + jq) * 17 + cp * 8 + rr) << 1) + e];
                }
                float reset = sigm(R);
                float cand  = tanhf(reset * C);
                float upd   = sigm(U);
                float dprev = xd_f[((200 + gd) * 8 + rr) * 2];
                float dnv = upd * cand + (1.0f - upd) * dprev;
                ull dv = dup2(dnv);
                dn_u[gd * 8 + rr] = dv;
                st_peer_u64(base32 + DN_OFF + (uint32_t)(gd * 8 + rr) * 8, peer, dv);
            }
            mbar_arrive_peer(mb_dn, peer);
        }
        __syncthreads();
        mbar_wait(mb_dn, ph);   // dn full everywhere (acquire)

        // ---- P3: h/ho partials ∥ deter out + carry ----
        if (tid < 400) {
            const int grp = tid % 50;
            const int z = tid / 50;
            const int rh = z & 1, seg = z >> 1;
            const float* W = (grp < 25)
                ? (w_img + (int)p * 100 + grp * 4)
                : (w_obsd + (int)p * 100 + (grp - 25) * 4);
            const ulonglong2* Wp = reinterpret_cast<const ulonglong2*>(W)
                                   + (size_t)(seg * 50) * 50;
            const ulonglong2* Ap = dn_u2 + (seg * 50) * 4 + rh * 2;
            ull A0 = 0, A1 = 0, A2 = 0, A3 = 0, A4 = 0, A5 = 0, A6 = 0, A7 = 0;
#pragma unroll 5
            for (int kk = 0; kk < 50; kk++) {
                ulonglong2 w = Wp[(size_t)kk * 50];
                ulonglong2 a01 = Ap[kk * 4];
                ulonglong2 a23 = Ap[kk * 4 + 1];
                fma2(A0, w.x, a01.x); fma2(A1, w.y, a01.x);
                fma2(A2, w.x, a01.y); fma2(A3, w.y, a01.y);
                fma2(A4, w.x, a23.x); fma2(A5, w.y, a23.x);
                fma2(A6, w.x, a23.y); fma2(A7, w.y, a23.y);
            }
            ull* P = part_u + (seg * 50 + grp) * 17 + rh * 4;
            P[0] = A0; P[8] = A1; P[1] = A2; P[9] = A3;
            P[2] = A4; P[10] = A5; P[3] = A6; P[11] = A7;
        } else {
            const int tt2 = tid - 400;
            for (int i = tt2; i < 800; i += 240) {
                const int rl = i / 200, j = i % 200;
                const int r = (int)p * 4 + rl;
                out[((size_t)(b0 + r) * Tc + t) * OUTC + 180 + j] =
                    dn_f[(j * 8 + r) * 2];
            }
            for (int i = tt2; i < 1600; i += 240) xd_u[1600 + i] = dn_u[i];
        }
        __syncthreads();

        // ---- C3: reduce + bias/pre_obs + elu -> hho, dup local + peer ----
        if (tid < 400) {
            const int cl = tid >> 1;
            const int rh = (tid & 1) * 4;
            const bool ish = cl < 100;
            const int gcol = (int)p * 100 + (ish ? cl : cl - 100);
            const int grp = ish ? (cl >> 2) : (25 + ((cl - 100) >> 2));
            const int ci = cl & 3, cp = ci >> 1, e = ci & 1;
            const float* po = g_pre_obs + ((size_t)t * Bc + b0) * Hc + gcol;
            const float bb = ish ? bimg[gcol] : 0.0f;
            const int dsti = ish ? gcol : 200 + gcol;
#pragma unroll
            for (int i = 0; i < 4; i++) {
                const int r = rh + i;
                float v = ish ? bb : po[r * Hc];
#pragma unroll
                for (int seg = 0; seg < 4; seg++)
                    v += part_f[(((seg * 50 + grp) * 17 + cp * 8 + r) << 1) + e];
                ull dv = dup2(eluf(v));
                hho_u[dsti * 8 + r] = dv;
                st_peer_u64(base32 + HHO_OFF + (uint32_t)(dsti * 8 + r) * 8, peer, dv);
            }
            mbar_arrive_peer(mb_hho, peer);
        }
        __syncthreads();
        mbar_wait(mb_hho, ph);  // hho full everywhere

        // ---- P4: stats partials ----
        if (tid < 240) {
            const int grp = tid % 15;
            const int z = tid / 15;
            const int rh = z & 1, seg = z >> 1;
            const float* W = (p ? w_obst : w_ims) + grp * 4;
            const ulonglong2* Wp = reinterpret_cast<const ulonglong2*>(W)
                                   + (size_t)(seg * 25) * 15;
            const ulonglong2* Ap = hho_u2 + (int)p * 800 + (seg * 25) * 4 + rh * 2;
            ull A0 = 0, A1 = 0, A2 = 0, A3 = 0, A4 = 0, A5 = 0, A6 = 0, A7 = 0;
#pragma unroll 5
            for (int kk = 0; kk < 25; kk++) {
                ulonglong2 w = Wp[(size_t)kk * 15];
                ulonglong2 a01 = Ap[kk * 4];
                ulonglong2 a23 = Ap[kk * 4 + 1];
                fma2(A0, w.x, a01.x); fma2(A1, w.y, a01.x);
                fma2(A2, w.x, a01.y); fma2(A3, w.y, a01.y);
                fma2(A4, w.x, a23.x); fma2(A5, w.y, a23.x);
                fma2(A6, w.x, a23.y); fma2(A7, w.y, a23.y);
            }
            ull* P = part_u + (seg * 15 + grp) * 17 + rh * 4;
            P[0] = A0; P[8] = A1; P[1] = A2; P[9] = A3;
            P[2] = A4; P[10] = A5; P[3] = A6; P[11] = A7;
        }
        __syncthreads();

        // ---- C4: reduce -> stat array, dup to peer ----
        if (tid < 240) {
            const int col = tid >> 2, q = tid & 3;
            const int cgq = col >> 2, ci = col & 3, cp = ci >> 1, e = ci & 1;
            const float bb = p ? bobs[col] : bims[col];
            const uint32_t dstoff = p ? SOS_OFF : STS_OFF;
            float* dst = reinterpret_cast<float*>(sm + dstoff);
#pragma unroll
            for (int w2 = 0; w2 < 2; w2++) {
                const int rr = q * 2 + w2;
                float v = bb;
#pragma unroll
                for (int seg = 0; seg < 8; seg++)
                    v += part_f[(((seg * 15 + cgq) * 17 + cp * 8 + rr) << 1) + e];
                dst[rr * 64 + col] = v;
                st_peer_f32(base32 + dstoff + (uint32_t)(rr * 64 + col) * 4, peer, v);
            }
            mbar_arrive_peer(mb_st, peer);
        }
        __syncthreads();
        mbar_wait(mb_st, ph);   // stS/soS full everywhere

        // ---- P5: sample, outputs, carry ----
        if (tid < 240) {
            const int r = tid / 30, k = tid - r * 30;
            const int b = b0 + r;
            float om  = soS[r * 64 + k];
            float osv = softplusf(soS[r * 64 + 30 + k]) + 0.1f;
            float ost = fmaf(osv, noise_o[((size_t)t * Bc + b) * Sc + k], om);
            st_f[k * 8 + r] = ost;
            if ((r >> 2) == (int)p) {
                float pm  = stS[r * 64 + k];
                float psv = softplusf(stS[r * 64 + 30 + k]) + 0.1f;
                float pst = fmaf(psv, noise_p[((size_t)t * Bc + b) * Sc + k], pm);
                size_t basep = ((size_t)b * Tc + t) * OUTC;
                out[basep + k]       = om;
                out[basep + 30 + k]  = osv;
                out[basep + 60 + k]  = ost;
                out[basep + 90 + k]  = pm;
                out[basep + 120 + k] = psv;
                out[basep + 150 + k] = pst;
            }
        }
        __syncthreads();
        ph ^= 1;
    }
}

// ===========================================================================
extern "C" void kernel_launch(void* const* d_in, const int* in_sizes, int n_in,
                              void* d_out, int out_size) {
    const float* embed       = (const float*)d_in[0];
    const float* action      = (const float*)d_in[1];
    const float* context     = (const float*)d_in[2];
    const float* noise_prior = (const float*)d_in[3];
    const float* noise_post  = (const float*)d_in[4];
    const float* w_inp       = (const float*)d_in[5];
    const float* b_inp       = (const float*)d_in[6];
    const float* w_gru       = (const float*)d_in[7];
    const float* b_gru       = (const float*)d_in[8];
    const float* w_img_out   = (const float*)d_in[9];
    const float* b_img_out   = (const float*)d_in[10];
    const float* w_obs_out   = (const float*)d_in[11];
    const float* b_obs_out   = (const float*)d_in[12];
    const float* w_ims_stat  = (const float*)d_in[13];
    const float* b_ims_stat  = (const float*)d_in[14];
    const float* w_obs_stat  = (const float*)d_in[15];
    const float* b_obs_stat  = (const float*)d_in[16];
    float* out = (float*)d_out;

    static int smem_set = 0;
    if (!smem_set) {
        cudaFuncSetAttribute(k_rssm, cudaFuncAttributeMaxDynamicSharedMemorySize,
                             SMEM_BYTES);
        smem_set = 1;
    }

    k_pre<<<512, 512>>>(embed, context, action, w_obs_out, b_obs_out,
                        w_inp, b_inp);
    k_rssm<<<128, 640, SMEM_BYTES>>>(noise_prior, noise_post, w_inp, w_gru,
                                     b_gru, w_img_out, b_img_out, w_obs_out,
                                     w_ims_stat, b_ims_stat, w_obs_stat,
                                     b_obs_stat, out);
}